// round 2
// baseline (speedup 1.0000x reference)
#include <cuda_runtime.h>
#include <cuda_bf16.h>

#define NN 100000
#define EE 1600000
#define CC 64
#define DD 512
#define KHOPS 10

// ---- device scratch (static allocation is the allowed mechanism) ----
__device__ float g_h[NN * CC];      // MLP output == hop-0 features
__device__ float g_bufA[NN * CC];   // ping
__device__ float g_bufB[NN * CC];   // pong
__device__ float g_acc[NN * CC];    // gated accumulator
__device__ int   g_deg[NN];
__device__ int   g_rowptr[NN + 1];
__device__ int   g_cursor[NN];
__device__ int2  g_edges[EE];       // .x = src, .y = float bits of weight

// ---------------- preprocessing: CSR by destination ----------------

__global__ void zero_kernel(int n) {
    int i = blockIdx.x * blockDim.x + threadIdx.x;
    if (i < n) { g_deg[i] = 0; g_cursor[i] = 0; }
}

__global__ void count_kernel(const int* __restrict__ dst, int e) {
    int i = blockIdx.x * blockDim.x + threadIdx.x;
    if (i < e) atomicAdd(&g_deg[dst[i]], 1);
}

// single-block two-pass scan: 1024 threads, ~98 elems each
__global__ void scan_kernel(int n) {
    __shared__ int s[1024];
    int t = threadIdx.x;
    int chunk = (n + 1023) >> 10;
    int s0 = t * chunk;
    int s1 = min(s0 + chunk, n);
    int sum = 0;
    for (int i = s0; i < s1; i++) sum += g_deg[i];
    s[t] = sum;
    __syncthreads();
    // Hillis-Steele inclusive scan
    for (int off = 1; off < 1024; off <<= 1) {
        int add = (t >= off) ? s[t - off] : 0;
        __syncthreads();
        s[t] += add;
        __syncthreads();
    }
    int run = (t > 0) ? s[t - 1] : 0;
    for (int i = s0; i < s1; i++) { g_rowptr[i] = run; run += g_deg[i]; }
    if (t == 1023) g_rowptr[n] = s[1023];
}

__global__ void fill_kernel(const int* __restrict__ src, const int* __restrict__ dst,
                            const float* __restrict__ w, int e) {
    int i = blockIdx.x * blockDim.x + threadIdx.x;
    if (i < e) {
        int d = dst[i];
        int pos = atomicAdd(&g_cursor[d], 1);
        g_edges[g_rowptr[d] + pos] = make_int2(src[i], __float_as_int(w[i]));
    }
}

// ---------------- fused 2-layer MLP: h = relu(relu(x@W1)@W2) ----------------
// block: 256 threads = 16x16, 64-row tile, full 64-wide output in registers (4x4/thread)

__global__ __launch_bounds__(256) void mlp_kernel(const float* __restrict__ x,
                                                  const float* __restrict__ W1,
                                                  const float* __restrict__ W2,
                                                  int n) {
    __shared__ float xs[64][65];   // x chunk / later h1 tile
    __shared__ float ws[64][68];   // W chunk (68 pad -> 16B-aligned rows for float4 LDS)

    int tid = threadIdx.x;
    int tx = tid & 15;
    int ty = tid >> 4;
    int row0 = blockIdx.x * 64;

    float acc[4][4];
#pragma unroll
    for (int i = 0; i < 4; i++)
#pragma unroll
        for (int j = 0; j < 4; j++) acc[i][j] = 0.f;

    // ---- stage 1: h1 = relu(x @ W1), K = 512 in chunks of 64 ----
    for (int k0 = 0; k0 < DD; k0 += 64) {
        for (int p = tid; p < 1024; p += 256) {
            int r = p >> 4, c4 = p & 15;
            float4 v = make_float4(0.f, 0.f, 0.f, 0.f);
            if (row0 + r < n)
                v = *(const float4*)&x[(row0 + r) * DD + k0 + c4 * 4];
            xs[r][c4 * 4 + 0] = v.x; xs[r][c4 * 4 + 1] = v.y;
            xs[r][c4 * 4 + 2] = v.z; xs[r][c4 * 4 + 3] = v.w;
        }
        for (int p = tid; p < 1024; p += 256) {
            int r = p >> 4, c4 = p & 15;
            *(float4*)&ws[r][c4 * 4] = *(const float4*)&W1[(k0 + r) * CC + c4 * 4];
        }
        __syncthreads();
#pragma unroll 8
        for (int kk = 0; kk < 64; kk++) {
            float a0 = xs[ty * 4 + 0][kk];
            float a1 = xs[ty * 4 + 1][kk];
            float a2 = xs[ty * 4 + 2][kk];
            float a3 = xs[ty * 4 + 3][kk];
            float4 b = *(const float4*)&ws[kk][tx * 4];
            acc[0][0] = fmaf(a0, b.x, acc[0][0]); acc[0][1] = fmaf(a0, b.y, acc[0][1]);
            acc[0][2] = fmaf(a0, b.z, acc[0][2]); acc[0][3] = fmaf(a0, b.w, acc[0][3]);
            acc[1][0] = fmaf(a1, b.x, acc[1][0]); acc[1][1] = fmaf(a1, b.y, acc[1][1]);
            acc[1][2] = fmaf(a1, b.z, acc[1][2]); acc[1][3] = fmaf(a1, b.w, acc[1][3]);
            acc[2][0] = fmaf(a2, b.x, acc[2][0]); acc[2][1] = fmaf(a2, b.y, acc[2][1]);
            acc[2][2] = fmaf(a2, b.z, acc[2][2]); acc[2][3] = fmaf(a2, b.w, acc[2][3]);
            acc[3][0] = fmaf(a3, b.x, acc[3][0]); acc[3][1] = fmaf(a3, b.y, acc[3][1]);
            acc[3][2] = fmaf(a3, b.z, acc[3][2]); acc[3][3] = fmaf(a3, b.w, acc[3][3]);
        }
        __syncthreads();
    }

    // relu -> stash h1 tile in xs
#pragma unroll
    for (int i = 0; i < 4; i++)
#pragma unroll
        for (int j = 0; j < 4; j++)
            xs[ty * 4 + i][tx * 4 + j] = fmaxf(acc[i][j], 0.f);

    for (int p = tid; p < 1024; p += 256) {
        int r = p >> 4, c4 = p & 15;
        *(float4*)&ws[r][c4 * 4] = *(const float4*)&W2[r * CC + c4 * 4];
    }
    // reset accumulators (reuse registers)
#pragma unroll
    for (int i = 0; i < 4; i++)
#pragma unroll
        for (int j = 0; j < 4; j++) acc[i][j] = 0.f;
    __syncthreads();

    // ---- stage 2: h = relu(h1 @ W2), K = 64 ----
#pragma unroll 8
    for (int kk = 0; kk < 64; kk++) {
        float a0 = xs[ty * 4 + 0][kk];
        float a1 = xs[ty * 4 + 1][kk];
        float a2 = xs[ty * 4 + 2][kk];
        float a3 = xs[ty * 4 + 3][kk];
        float4 b = *(const float4*)&ws[kk][tx * 4];
        acc[0][0] = fmaf(a0, b.x, acc[0][0]); acc[0][1] = fmaf(a0, b.y, acc[0][1]);
        acc[0][2] = fmaf(a0, b.z, acc[0][2]); acc[0][3] = fmaf(a0, b.w, acc[0][3]);
        acc[1][0] = fmaf(a1, b.x, acc[1][0]); acc[1][1] = fmaf(a1, b.y, acc[1][1]);
        acc[1][2] = fmaf(a1, b.z, acc[1][2]); acc[1][3] = fmaf(a1, b.w, acc[1][3]);
        acc[2][0] = fmaf(a2, b.x, acc[2][0]); acc[2][1] = fmaf(a2, b.y, acc[2][1]);
        acc[2][2] = fmaf(a2, b.z, acc[2][2]); acc[2][3] = fmaf(a2, b.w, acc[2][3]);
        acc[3][0] = fmaf(a3, b.x, acc[3][0]); acc[3][1] = fmaf(a3, b.y, acc[3][1]);
        acc[3][2] = fmaf(a3, b.z, acc[3][2]); acc[3][3] = fmaf(a3, b.w, acc[3][3]);
    }

#pragma unroll
    for (int i = 0; i < 4; i++) {
        int r = row0 + ty * 4 + i;
        if (r < n) {
#pragma unroll
            for (int j = 0; j < 4; j++)
                g_h[r * CC + tx * 4 + j] = fmaxf(acc[i][j], 0.f);
        }
    }
}

// ---------------- hop-0 gating: acc = sigmoid(h . wp) * h ----------------
__global__ void init_acc_kernel(const float* __restrict__ wp, int n) {
    int w = (blockIdx.x * blockDim.x + threadIdx.x) >> 5;
    int lane = threadIdx.x & 31;
    if (w >= n) return;
    float2 v = *(const float2*)&g_h[w * CC + lane * 2];
    float p = v.x * __ldg(&wp[lane * 2]) + v.y * __ldg(&wp[lane * 2 + 1]);
#pragma unroll
    for (int o = 16; o; o >>= 1) p += __shfl_xor_sync(0xffffffffu, p, o);
    float s = 1.f / (1.f + __expf(-p));
    float2 a; a.x = s * v.x; a.y = s * v.y;
    *(float2*)&g_acc[w * CC + lane * 2] = a;
}

// ---------------- SpMM hop: warp per dst row, fused DAGNN gating ----------------
__global__ __launch_bounds__(256) void spmm_kernel(int hop, const float* __restrict__ wp, int n) {
    const float* __restrict__ cur = (hop == 0) ? g_h : ((hop & 1) ? g_bufA : g_bufB);
    float* __restrict__ nxt = (hop & 1) ? g_bufB : g_bufA;

    int w = (blockIdx.x * blockDim.x + threadIdx.x) >> 5;
    int lane = threadIdx.x & 31;
    if (w >= n) return;

    int beg = g_rowptr[w];
    int end = g_rowptr[w + 1];
    float a0 = 0.f, a1 = 0.f;

    int e = beg;
    for (; e + 1 < end; e += 2) {
        int2 e0 = g_edges[e];
        int2 e1 = g_edges[e + 1];
        float2 v0 = *(const float2*)&cur[e0.x * CC + lane * 2];
        float2 v1 = *(const float2*)&cur[e1.x * CC + lane * 2];
        float w0 = __int_as_float(e0.y);
        float w1 = __int_as_float(e1.y);
        a0 = fmaf(w0, v0.x, a0); a1 = fmaf(w0, v0.y, a1);
        a0 = fmaf(w1, v1.x, a0); a1 = fmaf(w1, v1.y, a1);
    }
    if (e < end) {
        int2 e0 = g_edges[e];
        float2 v0 = *(const float2*)&cur[e0.x * CC + lane * 2];
        float w0 = __int_as_float(e0.y);
        a0 = fmaf(w0, v0.x, a0); a1 = fmaf(w0, v0.y, a1);
    }

    *(float2*)&nxt[w * CC + lane * 2] = make_float2(a0, a1);

    // fused gating: acc += sigmoid(row . wp) * row
    float p = a0 * __ldg(&wp[lane * 2]) + a1 * __ldg(&wp[lane * 2 + 1]);
#pragma unroll
    for (int o = 16; o; o >>= 1) p += __shfl_xor_sync(0xffffffffu, p, o);
    float s = 1.f / (1.f + __expf(-p));
    float2* ap = (float2*)&g_acc[w * CC + lane * 2];
    float2 av = *ap;
    av.x = fmaf(s, a0, av.x);
    av.y = fmaf(s, a1, av.y);
    *ap = av;
}

// ---------------- final gather ----------------
__global__ void gather_kernel(const int* __restrict__ idx, float* __restrict__ out, int ni) {
    int w = (blockIdx.x * blockDim.x + threadIdx.x) >> 5;
    int lane = threadIdx.x & 31;
    if (w >= ni) return;
    int nd = idx[w];
    *(float2*)&out[w * CC + lane * 2] = *(const float2*)&g_acc[nd * CC + lane * 2];
}

extern "C" void kernel_launch(void* const* d_in, const int* in_sizes, int n_in,
                              void* d_out, int out_size) {
    const float* x    = (const float*)d_in[0];
    const int*   esrc = (const int*)d_in[1];
    const int*   edst = (const int*)d_in[2];
    const float* ew   = (const float*)d_in[3];
    const int*   nidx = (const int*)d_in[4];
    const float* W1   = (const float*)d_in[5];
    const float* W2   = (const float*)d_in[6];
    const float* wp   = (const float*)d_in[7];

    int N  = in_sizes[0] / DD;
    int E  = in_sizes[1];
    int NI = in_sizes[4];

    // CSR-by-dst build (re-done every replay; device state must be reset)
    zero_kernel<<<(N + 255) / 256, 256>>>(N);
    count_kernel<<<(E + 255) / 256, 256>>>(edst, E);
    scan_kernel<<<1, 1024>>>(N);
    fill_kernel<<<(E + 255) / 256, 256>>>(esrc, edst, ew, E);

    // MLP -> g_h
    mlp_kernel<<<(N + 63) / 64, 256>>>(x, W1, W2, N);

    // hop 0 gating
    init_acc_kernel<<<(N * 32 + 255) / 256, 256>>>(wp, N);

    // 10 propagation hops with fused gating
    for (int k = 0; k < KHOPS; k++)
        spmm_kernel<<<(N * 32 + 255) / 256, 256>>>(k, wp, N);

    gather_kernel<<<(NI * 32 + 255) / 256, 256>>>(nidx, (float*)d_out, NI);
}

// round 3
// speedup vs baseline: 1.0011x; 1.0011x over previous
#include <cuda_runtime.h>
#include <cuda_bf16.h>

#define NN 100000
#define EE 1600000
#define CC 64
#define DD 512
#define KHOPS 10

// ---- device scratch (static allocation is the allowed mechanism) ----
__device__ float g_h[NN * CC];      // MLP output == hop-0 features
__device__ float g_bufA[NN * CC];   // ping
__device__ float g_bufB[NN * CC];   // pong
__device__ float g_acc[NN * CC];    // gated accumulator
__device__ int   g_deg[NN];
__device__ int   g_rowptr[NN + 1];
__device__ int   g_cursor[NN];
__device__ int2  g_edges[EE];       // .x = src, .y = float bits of weight

// ---------------- preprocessing: CSR by destination ----------------

__global__ void zero_kernel(int n) {
    int i = blockIdx.x * blockDim.x + threadIdx.x;
    if (i < n) { g_deg[i] = 0; g_cursor[i] = 0; }
}

__global__ void count_kernel(const int* __restrict__ dst, int e) {
    int i = blockIdx.x * blockDim.x + threadIdx.x;
    if (i < e) atomicAdd(&g_deg[dst[i]], 1);
}

// single-block two-pass scan: 1024 threads, ~98 elems each
__global__ void scan_kernel(int n) {
    __shared__ int s[1024];
    int t = threadIdx.x;
    int chunk = (n + 1023) >> 10;
    int s0 = t * chunk;
    int s1 = min(s0 + chunk, n);
    int sum = 0;
    for (int i = s0; i < s1; i++) sum += g_deg[i];
    s[t] = sum;
    __syncthreads();
    // Hillis-Steele inclusive scan
    for (int off = 1; off < 1024; off <<= 1) {
        int add = (t >= off) ? s[t - off] : 0;
        __syncthreads();
        s[t] += add;
        __syncthreads();
    }
    int run = (t > 0) ? s[t - 1] : 0;
    for (int i = s0; i < s1; i++) { g_rowptr[i] = run; run += g_deg[i]; }
    if (t == 1023) g_rowptr[n] = s[1023];
}

__global__ void fill_kernel(const int* __restrict__ src, const int* __restrict__ dst,
                            const float* __restrict__ w, int e) {
    int i = blockIdx.x * blockDim.x + threadIdx.x;
    if (i < e) {
        int d = dst[i];
        int pos = atomicAdd(&g_cursor[d], 1);
        g_edges[g_rowptr[d] + pos] = make_int2(src[i], __float_as_int(w[i]));
    }
}

// ---------------- fused 2-layer MLP: h = relu(relu(x@W1)@W2) ----------------
// block: 256 threads = 16x16, 64-row tile, full 64-wide output in registers (4x4/thread)

__global__ __launch_bounds__(256) void mlp_kernel(const float* __restrict__ x,
                                                  const float* __restrict__ W1,
                                                  const float* __restrict__ W2,
                                                  int n) {
    __shared__ float xs[64][65];   // x chunk / later h1 tile
    __shared__ float ws[64][68];   // W chunk (68 pad -> 16B-aligned rows for float4 LDS)

    int tid = threadIdx.x;
    int tx = tid & 15;
    int ty = tid >> 4;
    int row0 = blockIdx.x * 64;

    float acc[4][4];
#pragma unroll
    for (int i = 0; i < 4; i++)
#pragma unroll
        for (int j = 0; j < 4; j++) acc[i][j] = 0.f;

    // ---- stage 1: h1 = relu(x @ W1), K = 512 in chunks of 64 ----
    for (int k0 = 0; k0 < DD; k0 += 64) {
        for (int p = tid; p < 1024; p += 256) {
            int r = p >> 4, c4 = p & 15;
            float4 v = make_float4(0.f, 0.f, 0.f, 0.f);
            if (row0 + r < n)
                v = *(const float4*)&x[(row0 + r) * DD + k0 + c4 * 4];
            xs[r][c4 * 4 + 0] = v.x; xs[r][c4 * 4 + 1] = v.y;
            xs[r][c4 * 4 + 2] = v.z; xs[r][c4 * 4 + 3] = v.w;
        }
        for (int p = tid; p < 1024; p += 256) {
            int r = p >> 4, c4 = p & 15;
            *(float4*)&ws[r][c4 * 4] = *(const float4*)&W1[(k0 + r) * CC + c4 * 4];
        }
        __syncthreads();
#pragma unroll 8
        for (int kk = 0; kk < 64; kk++) {
            float a0 = xs[ty * 4 + 0][kk];
            float a1 = xs[ty * 4 + 1][kk];
            float a2 = xs[ty * 4 + 2][kk];
            float a3 = xs[ty * 4 + 3][kk];
            float4 b = *(const float4*)&ws[kk][tx * 4];
            acc[0][0] = fmaf(a0, b.x, acc[0][0]); acc[0][1] = fmaf(a0, b.y, acc[0][1]);
            acc[0][2] = fmaf(a0, b.z, acc[0][2]); acc[0][3] = fmaf(a0, b.w, acc[0][3]);
            acc[1][0] = fmaf(a1, b.x, acc[1][0]); acc[1][1] = fmaf(a1, b.y, acc[1][1]);
            acc[1][2] = fmaf(a1, b.z, acc[1][2]); acc[1][3] = fmaf(a1, b.w, acc[1][3]);
            acc[2][0] = fmaf(a2, b.x, acc[2][0]); acc[2][1] = fmaf(a2, b.y, acc[2][1]);
            acc[2][2] = fmaf(a2, b.z, acc[2][2]); acc[2][3] = fmaf(a2, b.w, acc[2][3]);
            acc[3][0] = fmaf(a3, b.x, acc[3][0]); acc[3][1] = fmaf(a3, b.y, acc[3][1]);
            acc[3][2] = fmaf(a3, b.z, acc[3][2]); acc[3][3] = fmaf(a3, b.w, acc[3][3]);
        }
        __syncthreads();
    }

    // relu -> stash h1 tile in xs
#pragma unroll
    for (int i = 0; i < 4; i++)
#pragma unroll
        for (int j = 0; j < 4; j++)
            xs[ty * 4 + i][tx * 4 + j] = fmaxf(acc[i][j], 0.f);

    for (int p = tid; p < 1024; p += 256) {
        int r = p >> 4, c4 = p & 15;
        *(float4*)&ws[r][c4 * 4] = *(const float4*)&W2[r * CC + c4 * 4];
    }
    // reset accumulators (reuse registers)
#pragma unroll
    for (int i = 0; i < 4; i++)
#pragma unroll
        for (int j = 0; j < 4; j++) acc[i][j] = 0.f;
    __syncthreads();

    // ---- stage 2: h = relu(h1 @ W2), K = 64 ----
#pragma unroll 8
    for (int kk = 0; kk < 64; kk++) {
        float a0 = xs[ty * 4 + 0][kk];
        float a1 = xs[ty * 4 + 1][kk];
        float a2 = xs[ty * 4 + 2][kk];
        float a3 = xs[ty * 4 + 3][kk];
        float4 b = *(const float4*)&ws[kk][tx * 4];
        acc[0][0] = fmaf(a0, b.x, acc[0][0]); acc[0][1] = fmaf(a0, b.y, acc[0][1]);
        acc[0][2] = fmaf(a0, b.z, acc[0][2]); acc[0][3] = fmaf(a0, b.w, acc[0][3]);
        acc[1][0] = fmaf(a1, b.x, acc[1][0]); acc[1][1] = fmaf(a1, b.y, acc[1][1]);
        acc[1][2] = fmaf(a1, b.z, acc[1][2]); acc[1][3] = fmaf(a1, b.w, acc[1][3]);
        acc[2][0] = fmaf(a2, b.x, acc[2][0]); acc[2][1] = fmaf(a2, b.y, acc[2][1]);
        acc[2][2] = fmaf(a2, b.z, acc[2][2]); acc[2][3] = fmaf(a2, b.w, acc[2][3]);
        acc[3][0] = fmaf(a3, b.x, acc[3][0]); acc[3][1] = fmaf(a3, b.y, acc[3][1]);
        acc[3][2] = fmaf(a3, b.z, acc[3][2]); acc[3][3] = fmaf(a3, b.w, acc[3][3]);
    }

#pragma unroll
    for (int i = 0; i < 4; i++) {
        int r = row0 + ty * 4 + i;
        if (r < n) {
#pragma unroll
            for (int j = 0; j < 4; j++)
                g_h[r * CC + tx * 4 + j] = fmaxf(acc[i][j], 0.f);
        }
    }
}

// ---------------- hop-0 gating: acc = sigmoid(h . wp) * h ----------------
__global__ void init_acc_kernel(const float* __restrict__ wp, int n) {
    int w = (blockIdx.x * blockDim.x + threadIdx.x) >> 5;
    int lane = threadIdx.x & 31;
    if (w >= n) return;
    float2 v = *(const float2*)&g_h[w * CC + lane * 2];
    float p = v.x * __ldg(&wp[lane * 2]) + v.y * __ldg(&wp[lane * 2 + 1]);
#pragma unroll
    for (int o = 16; o; o >>= 1) p += __shfl_xor_sync(0xffffffffu, p, o);
    float s = 1.f / (1.f + __expf(-p));
    float2 a; a.x = s * v.x; a.y = s * v.y;
    *(float2*)&g_acc[w * CC + lane * 2] = a;
}

// ---------------- SpMM hop: warp per dst row, fused DAGNN gating ----------------
__global__ __launch_bounds__(256) void spmm_kernel(int hop, const float* __restrict__ wp, int n) {
    const float* __restrict__ cur = (hop == 0) ? g_h : ((hop & 1) ? g_bufA : g_bufB);
    float* __restrict__ nxt = (hop & 1) ? g_bufB : g_bufA;

    int w = (blockIdx.x * blockDim.x + threadIdx.x) >> 5;
    int lane = threadIdx.x & 31;
    if (w >= n) return;

    int beg = g_rowptr[w];
    int end = g_rowptr[w + 1];
    float a0 = 0.f, a1 = 0.f;

    int e = beg;
    for (; e + 1 < end; e += 2) {
        int2 e0 = g_edges[e];
        int2 e1 = g_edges[e + 1];
        float2 v0 = *(const float2*)&cur[e0.x * CC + lane * 2];
        float2 v1 = *(const float2*)&cur[e1.x * CC + lane * 2];
        float w0 = __int_as_float(e0.y);
        float w1 = __int_as_float(e1.y);
        a0 = fmaf(w0, v0.x, a0); a1 = fmaf(w0, v0.y, a1);
        a0 = fmaf(w1, v1.x, a0); a1 = fmaf(w1, v1.y, a1);
    }
    if (e < end) {
        int2 e0 = g_edges[e];
        float2 v0 = *(const float2*)&cur[e0.x * CC + lane * 2];
        float w0 = __int_as_float(e0.y);
        a0 = fmaf(w0, v0.x, a0); a1 = fmaf(w0, v0.y, a1);
    }

    *(float2*)&nxt[w * CC + lane * 2] = make_float2(a0, a1);

    // fused gating: acc += sigmoid(row . wp) * row
    float p = a0 * __ldg(&wp[lane * 2]) + a1 * __ldg(&wp[lane * 2 + 1]);
#pragma unroll
    for (int o = 16; o; o >>= 1) p += __shfl_xor_sync(0xffffffffu, p, o);
    float s = 1.f / (1.f + __expf(-p));
    float2* ap = (float2*)&g_acc[w * CC + lane * 2];
    float2 av = *ap;
    av.x = fmaf(s, a0, av.x);
    av.y = fmaf(s, a1, av.y);
    *ap = av;
}

// ---------------- final gather ----------------
__global__ void gather_kernel(const int* __restrict__ idx, float* __restrict__ out, int ni) {
    int w = (blockIdx.x * blockDim.x + threadIdx.x) >> 5;
    int lane = threadIdx.x & 31;
    if (w >= ni) return;
    int nd = idx[w];
    *(float2*)&out[w * CC + lane * 2] = *(const float2*)&g_acc[nd * CC + lane * 2];
}

extern "C" void kernel_launch(void* const* d_in, const int* in_sizes, int n_in,
                              void* d_out, int out_size) {
    const float* x    = (const float*)d_in[0];
    const int*   esrc = (const int*)d_in[1];
    const int*   edst = (const int*)d_in[2];
    const float* ew   = (const float*)d_in[3];
    const int*   nidx = (const int*)d_in[4];
    const float* W1   = (const float*)d_in[5];
    const float* W2   = (const float*)d_in[6];
    const float* wp   = (const float*)d_in[7];

    int N  = in_sizes[0] / DD;
    int E  = in_sizes[1];
    int NI = in_sizes[4];

    // CSR-by-dst build (re-done every replay; device state must be reset)
    zero_kernel<<<(N + 255) / 256, 256>>>(N);
    count_kernel<<<(E + 255) / 256, 256>>>(edst, E);
    scan_kernel<<<1, 1024>>>(N);
    fill_kernel<<<(E + 255) / 256, 256>>>(esrc, edst, ew, E);

    // MLP -> g_h
    mlp_kernel<<<(N + 63) / 64, 256>>>(x, W1, W2, N);

    // hop 0 gating
    init_acc_kernel<<<(N * 32 + 255) / 256, 256>>>(wp, N);

    // 10 propagation hops with fused gating
    for (int k = 0; k < KHOPS; k++)
        spmm_kernel<<<(N * 32 + 255) / 256, 256>>>(k, wp, N);

    gather_kernel<<<(NI * 32 + 255) / 256, 256>>>(nidx, (float*)d_out, NI);
}

// round 4
// speedup vs baseline: 1.0038x; 1.0027x over previous
#include <cuda_runtime.h>
#include <cuda_bf16.h>

#define NN 100000
#define EE 1600000
#define CC 64
#define DD 512
#define KHOPS 10

// ---- device scratch (static allocation is the allowed mechanism) ----
__device__ float g_h[NN * CC];      // MLP output == hop-0 features
__device__ float g_bufA[NN * CC];   // ping
__device__ float g_bufB[NN * CC];   // pong
__device__ float g_acc[NN * CC];    // gated accumulator
__device__ int   g_deg[NN];
__device__ int   g_rowptr[NN + 1];
__device__ int   g_cursor[NN];
__device__ int2  g_edges[EE];       // .x = src, .y = float bits of weight

// ---------------- preprocessing: CSR by destination ----------------

__global__ void zero_kernel(int n) {
    int i = blockIdx.x * blockDim.x + threadIdx.x;
    if (i < n) { g_deg[i] = 0; g_cursor[i] = 0; }
}

__global__ void count_kernel(const int* __restrict__ dst, int e) {
    int i = blockIdx.x * blockDim.x + threadIdx.x;
    if (i < e) atomicAdd(&g_deg[dst[i]], 1);
}

// single-block two-pass scan: 1024 threads, ~98 elems each
__global__ void scan_kernel(int n) {
    __shared__ int s[1024];
    int t = threadIdx.x;
    int chunk = (n + 1023) >> 10;
    int s0 = t * chunk;
    int s1 = min(s0 + chunk, n);
    int sum = 0;
    for (int i = s0; i < s1; i++) sum += g_deg[i];
    s[t] = sum;
    __syncthreads();
    // Hillis-Steele inclusive scan
    for (int off = 1; off < 1024; off <<= 1) {
        int add = (t >= off) ? s[t - off] : 0;
        __syncthreads();
        s[t] += add;
        __syncthreads();
    }
    int run = (t > 0) ? s[t - 1] : 0;
    for (int i = s0; i < s1; i++) { g_rowptr[i] = run; run += g_deg[i]; }
    if (t == 1023) g_rowptr[n] = s[1023];
}

__global__ void fill_kernel(const int* __restrict__ src, const int* __restrict__ dst,
                            const float* __restrict__ w, int e) {
    int i = blockIdx.x * blockDim.x + threadIdx.x;
    if (i < e) {
        int d = dst[i];
        int pos = atomicAdd(&g_cursor[d], 1);
        g_edges[g_rowptr[d] + pos] = make_int2(src[i], __float_as_int(w[i]));
    }
}

// ---------------- fused 2-layer MLP: h = relu(relu(x@W1)@W2) ----------------
// block: 256 threads = 16x16, 64-row tile, full 64-wide output in registers (4x4/thread)

__global__ __launch_bounds__(256) void mlp_kernel(const float* __restrict__ x,
                                                  const float* __restrict__ W1,
                                                  const float* __restrict__ W2,
                                                  int n) {
    __shared__ float xs[64][65];   // x chunk / later h1 tile
    __shared__ float ws[64][68];   // W chunk (68 pad -> 16B-aligned rows for float4 LDS)

    int tid = threadIdx.x;
    int tx = tid & 15;
    int ty = tid >> 4;
    int row0 = blockIdx.x * 64;

    float acc[4][4];
#pragma unroll
    for (int i = 0; i < 4; i++)
#pragma unroll
        for (int j = 0; j < 4; j++) acc[i][j] = 0.f;

    // ---- stage 1: h1 = relu(x @ W1), K = 512 in chunks of 64 ----
    for (int k0 = 0; k0 < DD; k0 += 64) {
        for (int p = tid; p < 1024; p += 256) {
            int r = p >> 4, c4 = p & 15;
            float4 v = make_float4(0.f, 0.f, 0.f, 0.f);
            if (row0 + r < n)
                v = *(const float4*)&x[(row0 + r) * DD + k0 + c4 * 4];
            xs[r][c4 * 4 + 0] = v.x; xs[r][c4 * 4 + 1] = v.y;
            xs[r][c4 * 4 + 2] = v.z; xs[r][c4 * 4 + 3] = v.w;
        }
        for (int p = tid; p < 1024; p += 256) {
            int r = p >> 4, c4 = p & 15;
            *(float4*)&ws[r][c4 * 4] = *(const float4*)&W1[(k0 + r) * CC + c4 * 4];
        }
        __syncthreads();
#pragma unroll 8
        for (int kk = 0; kk < 64; kk++) {
            float a0 = xs[ty * 4 + 0][kk];
            float a1 = xs[ty * 4 + 1][kk];
            float a2 = xs[ty * 4 + 2][kk];
            float a3 = xs[ty * 4 + 3][kk];
            float4 b = *(const float4*)&ws[kk][tx * 4];
            acc[0][0] = fmaf(a0, b.x, acc[0][0]); acc[0][1] = fmaf(a0, b.y, acc[0][1]);
            acc[0][2] = fmaf(a0, b.z, acc[0][2]); acc[0][3] = fmaf(a0, b.w, acc[0][3]);
            acc[1][0] = fmaf(a1, b.x, acc[1][0]); acc[1][1] = fmaf(a1, b.y, acc[1][1]);
            acc[1][2] = fmaf(a1, b.z, acc[1][2]); acc[1][3] = fmaf(a1, b.w, acc[1][3]);
            acc[2][0] = fmaf(a2, b.x, acc[2][0]); acc[2][1] = fmaf(a2, b.y, acc[2][1]);
            acc[2][2] = fmaf(a2, b.z, acc[2][2]); acc[2][3] = fmaf(a2, b.w, acc[2][3]);
            acc[3][0] = fmaf(a3, b.x, acc[3][0]); acc[3][1] = fmaf(a3, b.y, acc[3][1]);
            acc[3][2] = fmaf(a3, b.z, acc[3][2]); acc[3][3] = fmaf(a3, b.w, acc[3][3]);
        }
        __syncthreads();
    }

    // relu -> stash h1 tile in xs
#pragma unroll
    for (int i = 0; i < 4; i++)
#pragma unroll
        for (int j = 0; j < 4; j++)
            xs[ty * 4 + i][tx * 4 + j] = fmaxf(acc[i][j], 0.f);

    for (int p = tid; p < 1024; p += 256) {
        int r = p >> 4, c4 = p & 15;
        *(float4*)&ws[r][c4 * 4] = *(const float4*)&W2[r * CC + c4 * 4];
    }
    // reset accumulators (reuse registers)
#pragma unroll
    for (int i = 0; i < 4; i++)
#pragma unroll
        for (int j = 0; j < 4; j++) acc[i][j] = 0.f;
    __syncthreads();

    // ---- stage 2: h = relu(h1 @ W2), K = 64 ----
#pragma unroll 8
    for (int kk = 0; kk < 64; kk++) {
        float a0 = xs[ty * 4 + 0][kk];
        float a1 = xs[ty * 4 + 1][kk];
        float a2 = xs[ty * 4 + 2][kk];
        float a3 = xs[ty * 4 + 3][kk];
        float4 b = *(const float4*)&ws[kk][tx * 4];
        acc[0][0] = fmaf(a0, b.x, acc[0][0]); acc[0][1] = fmaf(a0, b.y, acc[0][1]);
        acc[0][2] = fmaf(a0, b.z, acc[0][2]); acc[0][3] = fmaf(a0, b.w, acc[0][3]);
        acc[1][0] = fmaf(a1, b.x, acc[1][0]); acc[1][1] = fmaf(a1, b.y, acc[1][1]);
        acc[1][2] = fmaf(a1, b.z, acc[1][2]); acc[1][3] = fmaf(a1, b.w, acc[1][3]);
        acc[2][0] = fmaf(a2, b.x, acc[2][0]); acc[2][1] = fmaf(a2, b.y, acc[2][1]);
        acc[2][2] = fmaf(a2, b.z, acc[2][2]); acc[2][3] = fmaf(a2, b.w, acc[2][3]);
        acc[3][0] = fmaf(a3, b.x, acc[3][0]); acc[3][1] = fmaf(a3, b.y, acc[3][1]);
        acc[3][2] = fmaf(a3, b.z, acc[3][2]); acc[3][3] = fmaf(a3, b.w, acc[3][3]);
    }

#pragma unroll
    for (int i = 0; i < 4; i++) {
        int r = row0 + ty * 4 + i;
        if (r < n) {
#pragma unroll
            for (int j = 0; j < 4; j++)
                g_h[r * CC + tx * 4 + j] = fmaxf(acc[i][j], 0.f);
        }
    }
}

// ---------------- hop-0 gating: acc = sigmoid(h . wp) * h ----------------
__global__ void init_acc_kernel(const float* __restrict__ wp, int n) {
    int w = (blockIdx.x * blockDim.x + threadIdx.x) >> 5;
    int lane = threadIdx.x & 31;
    if (w >= n) return;
    float2 v = *(const float2*)&g_h[w * CC + lane * 2];
    float p = v.x * __ldg(&wp[lane * 2]) + v.y * __ldg(&wp[lane * 2 + 1]);
#pragma unroll
    for (int o = 16; o; o >>= 1) p += __shfl_xor_sync(0xffffffffu, p, o);
    float s = 1.f / (1.f + __expf(-p));
    float2 a; a.x = s * v.x; a.y = s * v.y;
    *(float2*)&g_acc[w * CC + lane * 2] = a;
}

// ---------------- SpMM hop: warp per dst row, fused DAGNN gating ----------------
__global__ __launch_bounds__(256) void spmm_kernel(int hop, const float* __restrict__ wp, int n) {
    const float* __restrict__ cur = (hop == 0) ? g_h : ((hop & 1) ? g_bufA : g_bufB);
    float* __restrict__ nxt = (hop & 1) ? g_bufB : g_bufA;

    int w = (blockIdx.x * blockDim.x + threadIdx.x) >> 5;
    int lane = threadIdx.x & 31;
    if (w >= n) return;

    int beg = g_rowptr[w];
    int end = g_rowptr[w + 1];
    float a0 = 0.f, a1 = 0.f;

    int e = beg;
    for (; e + 1 < end; e += 2) {
        int2 e0 = g_edges[e];
        int2 e1 = g_edges[e + 1];
        float2 v0 = *(const float2*)&cur[e0.x * CC + lane * 2];
        float2 v1 = *(const float2*)&cur[e1.x * CC + lane * 2];
        float w0 = __int_as_float(e0.y);
        float w1 = __int_as_float(e1.y);
        a0 = fmaf(w0, v0.x, a0); a1 = fmaf(w0, v0.y, a1);
        a0 = fmaf(w1, v1.x, a0); a1 = fmaf(w1, v1.y, a1);
    }
    if (e < end) {
        int2 e0 = g_edges[e];
        float2 v0 = *(const float2*)&cur[e0.x * CC + lane * 2];
        float w0 = __int_as_float(e0.y);
        a0 = fmaf(w0, v0.x, a0); a1 = fmaf(w0, v0.y, a1);
    }

    *(float2*)&nxt[w * CC + lane * 2] = make_float2(a0, a1);

    // fused gating: acc += sigmoid(row . wp) * row
    float p = a0 * __ldg(&wp[lane * 2]) + a1 * __ldg(&wp[lane * 2 + 1]);
#pragma unroll
    for (int o = 16; o; o >>= 1) p += __shfl_xor_sync(0xffffffffu, p, o);
    float s = 1.f / (1.f + __expf(-p));
    float2* ap = (float2*)&g_acc[w * CC + lane * 2];
    float2 av = *ap;
    av.x = fmaf(s, a0, av.x);
    av.y = fmaf(s, a1, av.y);
    *ap = av;
}

// ---------------- final gather ----------------
__global__ void gather_kernel(const int* __restrict__ idx, float* __restrict__ out, int ni) {
    int w = (blockIdx.x * blockDim.x + threadIdx.x) >> 5;
    int lane = threadIdx.x & 31;
    if (w >= ni) return;
    int nd = idx[w];
    *(float2*)&out[w * CC + lane * 2] = *(const float2*)&g_acc[nd * CC + lane * 2];
}

extern "C" void kernel_launch(void* const* d_in, const int* in_sizes, int n_in,
                              void* d_out, int out_size) {
    const float* x    = (const float*)d_in[0];
    const int*   esrc = (const int*)d_in[1];
    const int*   edst = (const int*)d_in[2];
    const float* ew   = (const float*)d_in[3];
    const int*   nidx = (const int*)d_in[4];
    const float* W1   = (const float*)d_in[5];
    const float* W2   = (const float*)d_in[6];
    const float* wp   = (const float*)d_in[7];

    int N  = in_sizes[0] / DD;
    int E  = in_sizes[1];
    int NI = in_sizes[4];

    // CSR-by-dst build (re-done every replay; device state must be reset)
    zero_kernel<<<(N + 255) / 256, 256>>>(N);
    count_kernel<<<(E + 255) / 256, 256>>>(edst, E);
    scan_kernel<<<1, 1024>>>(N);
    fill_kernel<<<(E + 255) / 256, 256>>>(esrc, edst, ew, E);

    // MLP -> g_h
    mlp_kernel<<<(N + 63) / 64, 256>>>(x, W1, W2, N);

    // hop 0 gating
    init_acc_kernel<<<(N * 32 + 255) / 256, 256>>>(wp, N);

    // 10 propagation hops with fused gating
    for (int k = 0; k < KHOPS; k++)
        spmm_kernel<<<(N * 32 + 255) / 256, 256>>>(k, wp, N);

    gather_kernel<<<(NI * 32 + 255) / 256, 256>>>(nidx, (float*)d_out, NI);
}

// round 5
// speedup vs baseline: 1.2516x; 1.2469x over previous
#include <cuda_runtime.h>
#include <cuda_bf16.h>
#include <cstdint>

#define NN 100000
#define EE 1600000
#define CC 64
#define DD 512
#define KHOPS 10

// ---- device scratch ----
__device__ float g_H[(KHOPS + 1) * (size_t)NN * CC];  // all hop features (H[0] = MLP out)
__device__ int   g_deg[NN];
__device__ int   g_rowptr[NN + 1];
__device__ int   g_cursor[NN];
__device__ int2  g_edges[EE];       // .x = src, .y = float bits of weight

// ---------------- preprocessing: CSR by destination ----------------

__global__ void zero_kernel(int n) {
    int i = blockIdx.x * blockDim.x + threadIdx.x;
    if (i < n) { g_deg[i] = 0; g_cursor[i] = 0; }
}

__global__ void count_kernel(const int* __restrict__ dst, int e) {
    int i = blockIdx.x * blockDim.x + threadIdx.x;
    if (i < e) atomicAdd(&g_deg[dst[i]], 1);
}

__global__ void scan_kernel(int n) {
    __shared__ int s[1024];
    int t = threadIdx.x;
    int chunk = (n + 1023) >> 10;
    int s0 = t * chunk;
    int s1 = min(s0 + chunk, n);
    int sum = 0;
    for (int i = s0; i < s1; i++) sum += g_deg[i];
    s[t] = sum;
    __syncthreads();
    for (int off = 1; off < 1024; off <<= 1) {
        int add = (t >= off) ? s[t - off] : 0;
        __syncthreads();
        s[t] += add;
        __syncthreads();
    }
    int run = (t > 0) ? s[t - 1] : 0;
    for (int i = s0; i < s1; i++) { g_rowptr[i] = run; run += g_deg[i]; }
    if (t == 1023) g_rowptr[n] = s[1023];
}

__global__ void fill_kernel(const int* __restrict__ src, const int* __restrict__ dst,
                            const float* __restrict__ w, int e) {
    int i = blockIdx.x * blockDim.x + threadIdx.x;
    if (i < e) {
        int d = dst[i];
        int pos = atomicAdd(&g_cursor[d], 1);
        g_edges[g_rowptr[d] + pos] = make_int2(src[i], __float_as_int(w[i]));
    }
}

// ---------------- tensor-core MLP: h = relu(relu(x@W1)@W2) ----------------
// bf16 double-split (hi+lo), 3x mma.sync.m16n8k16 => ~fp32 precision.
// Block: 256 threads = 8 warps. Block tile: 256 rows x 64 cols. Warp: 32 rows.
// Dynamic smem layout (bytes):
//   [0      , 36864) : u_hi  (stage1 A_hi [256][40]bf16 = 20480 / stage2 h1_hi [256][72]bf16 = 36864)
//   [36864  , 73728) : u_lo  (same shapes)
//   [73728  , 78848) : B_hi  [64 n][40 k] bf16
//   [78848  , 83968) : B_lo
#define MLP_SMEM 83968
#define S1_STRIDE 40
#define S2_STRIDE 72

__device__ __forceinline__ void mma_bf16(float* c, uint32_t a0, uint32_t a1,
                                         uint32_t a2, uint32_t a3,
                                         uint32_t b0, uint32_t b1) {
    asm volatile(
        "mma.sync.aligned.m16n8k16.row.col.f32.bf16.bf16.f32 "
        "{%0,%1,%2,%3}, {%4,%5,%6,%7}, {%8,%9}, {%0,%1,%2,%3};\n"
        : "+f"(c[0]), "+f"(c[1]), "+f"(c[2]), "+f"(c[3])
        : "r"(a0), "r"(a1), "r"(a2), "r"(a3), "r"(b0), "r"(b1));
}

__device__ __forceinline__ void split2(float x, float y, uint32_t& hi, uint32_t& lo) {
    __nv_bfloat162 h2 = __floats2bfloat162_rn(x, y);
    float rx = x - __bfloat162float(h2.x);
    float ry = y - __bfloat162float(h2.y);
    __nv_bfloat162 l2 = __floats2bfloat162_rn(rx, ry);
    hi = *(uint32_t*)&h2;
    lo = *(uint32_t*)&l2;
}

__global__ __launch_bounds__(256) void mlp_mma_kernel(const float* __restrict__ x,
                                                      const float* __restrict__ W1,
                                                      const float* __restrict__ W2,
                                                      float* __restrict__ h_out,
                                                      int n) {
    extern __shared__ char sm[];
    __nv_bfloat16* uHi = (__nv_bfloat16*)sm;
    __nv_bfloat16* uLo = (__nv_bfloat16*)(sm + 36864);
    __nv_bfloat16* bHi = (__nv_bfloat16*)(sm + 73728);
    __nv_bfloat16* bLo = (__nv_bfloat16*)(sm + 78848);

    int tid  = threadIdx.x;
    int lane = tid & 31;
    int warp = tid >> 5;
    int g  = lane >> 2;     // 0..7
    int tg = lane & 3;      // 0..3
    int row0 = blockIdx.x * 256;
    int warpRow = warp * 32;

    float acc[2][8][4];
#pragma unroll
    for (int rg = 0; rg < 2; rg++)
#pragma unroll
        for (int nt = 0; nt < 8; nt++)
#pragma unroll
            for (int q = 0; q < 4; q++) acc[rg][nt][q] = 0.f;

    // ================= stage 1: h1 = relu(x @ W1), K = 512 in 16 chunks of 32 =================
    for (int kc = 0; kc < 16; kc++) {
        int k0 = kc * 32;
        __syncthreads();
        // load x chunk [256][32] -> split hi/lo (8 float4 per thread)
        for (int p = tid; p < 2048; p += 256) {
            int r = p >> 3, c4 = p & 7;
            float4 v = make_float4(0.f, 0.f, 0.f, 0.f);
            if (row0 + r < n)
                v = *(const float4*)&x[(size_t)(row0 + r) * DD + k0 + c4 * 4];
            uint32_t h0, l0, h1v, l1v;
            split2(v.x, v.y, h0, l0);
            split2(v.z, v.w, h1v, l1v);
            int base = r * S1_STRIDE + c4 * 4;       // bf16 index, even
            *(uint32_t*)&uHi[base]     = h0;
            *(uint32_t*)&uHi[base + 2] = h1v;
            *(uint32_t*)&uLo[base]     = l0;
            *(uint32_t*)&uLo[base + 2] = l1v;
        }
        // load W1 chunk [32 k][64 n] -> transposed B [n][k] hi/lo
        for (int p = tid; p < 512; p += 256) {
            int k = p >> 4, n4 = p & 15;
            float4 v = *(const float4*)&W1[(size_t)(k0 + k) * CC + n4 * 4];
            float vv[4] = {v.x, v.y, v.z, v.w};
#pragma unroll
            for (int j = 0; j < 4; j++) {
                int nn = n4 * 4 + j;
                __nv_bfloat16 h = __float2bfloat16(vv[j]);
                __nv_bfloat16 l = __float2bfloat16(vv[j] - __bfloat162float(h));
                bHi[nn * S1_STRIDE + k] = h;
                bLo[nn * S1_STRIDE + k] = l;
            }
        }
        __syncthreads();

#pragma unroll
        for (int ks = 0; ks < 2; ks++) {
            int kb = ks * 16;
            uint32_t aHi[2][4], aLo[2][4];
#pragma unroll
            for (int rg = 0; rg < 2; rg++) {
                int r = warpRow + rg * 16 + g;
                int i0 = r * S1_STRIDE + kb + tg * 2;
                int i1 = (r + 8) * S1_STRIDE + kb + tg * 2;
                aHi[rg][0] = *(uint32_t*)&uHi[i0];
                aHi[rg][1] = *(uint32_t*)&uHi[i1];
                aHi[rg][2] = *(uint32_t*)&uHi[i0 + 8];
                aHi[rg][3] = *(uint32_t*)&uHi[i1 + 8];
                aLo[rg][0] = *(uint32_t*)&uLo[i0];
                aLo[rg][1] = *(uint32_t*)&uLo[i1];
                aLo[rg][2] = *(uint32_t*)&uLo[i0 + 8];
                aLo[rg][3] = *(uint32_t*)&uLo[i1 + 8];
            }
#pragma unroll
            for (int nt = 0; nt < 8; nt++) {
                int bi = (nt * 8 + g) * S1_STRIDE + kb + tg * 2;
                uint32_t b0h = *(uint32_t*)&bHi[bi];
                uint32_t b1h = *(uint32_t*)&bHi[bi + 8];
                uint32_t b0l = *(uint32_t*)&bLo[bi];
                uint32_t b1l = *(uint32_t*)&bLo[bi + 8];
#pragma unroll
                for (int rg = 0; rg < 2; rg++) {
                    mma_bf16(acc[rg][nt], aHi[rg][0], aHi[rg][1], aHi[rg][2], aHi[rg][3], b0h, b1h);
                    mma_bf16(acc[rg][nt], aHi[rg][0], aHi[rg][1], aHi[rg][2], aHi[rg][3], b0l, b1l);
                    mma_bf16(acc[rg][nt], aLo[rg][0], aLo[rg][1], aLo[rg][2], aLo[rg][3], b0h, b1h);
                }
            }
        }
    }

    // ======= relu(h1) -> smem as bf16 hi/lo [256][72], reset acc =======
    __syncthreads();
#pragma unroll
    for (int rg = 0; rg < 2; rg++) {
        int r1 = warpRow + rg * 16 + g;
        int r2 = r1 + 8;
#pragma unroll
        for (int nt = 0; nt < 8; nt++) {
            int col = nt * 8 + tg * 2;
            float v0 = fmaxf(acc[rg][nt][0], 0.f);
            float v1 = fmaxf(acc[rg][nt][1], 0.f);
            float v2 = fmaxf(acc[rg][nt][2], 0.f);
            float v3 = fmaxf(acc[rg][nt][3], 0.f);
            uint32_t h, l;
            split2(v0, v1, h, l);
            *(uint32_t*)&uHi[r1 * S2_STRIDE + col] = h;
            *(uint32_t*)&uLo[r1 * S2_STRIDE + col] = l;
            split2(v2, v3, h, l);
            *(uint32_t*)&uHi[r2 * S2_STRIDE + col] = h;
            *(uint32_t*)&uLo[r2 * S2_STRIDE + col] = l;
#pragma unroll
            for (int q = 0; q < 4; q++) acc[rg][nt][q] = 0.f;
        }
    }
    __syncthreads();

    // ================= stage 2: h = relu(h1 @ W2), K = 64 in 2 chunks of 32 =================
    for (int c2 = 0; c2 < 2; c2++) {
        if (c2) __syncthreads();
        for (int p = tid; p < 512; p += 256) {
            int k = p >> 4, n4 = p & 15;
            float4 v = *(const float4*)&W2[(size_t)(c2 * 32 + k) * CC + n4 * 4];
            float vv[4] = {v.x, v.y, v.z, v.w};
#pragma unroll
            for (int j = 0; j < 4; j++) {
                int nn = n4 * 4 + j;
                __nv_bfloat16 h = __float2bfloat16(vv[j]);
                __nv_bfloat16 l = __float2bfloat16(vv[j] - __bfloat162float(h));
                bHi[nn * S1_STRIDE + k] = h;
                bLo[nn * S1_STRIDE + k] = l;
            }
        }
        __syncthreads();

#pragma unroll
        for (int ks = 0; ks < 2; ks++) {
            int kb = c2 * 32 + ks * 16;      // col in h1 buffer
            int kbb = ks * 16;               // k in B buffer
            uint32_t aHi[2][4], aLo[2][4];
#pragma unroll
            for (int rg = 0; rg < 2; rg++) {
                int r = warpRow + rg * 16 + g;
                int i0 = r * S2_STRIDE + kb + tg * 2;
                int i1 = (r + 8) * S2_STRIDE + kb + tg * 2;
                aHi[rg][0] = *(uint32_t*)&uHi[i0];
                aHi[rg][1] = *(uint32_t*)&uHi[i1];
                aHi[rg][2] = *(uint32_t*)&uHi[i0 + 8];
                aHi[rg][3] = *(uint32_t*)&uHi[i1 + 8];
                aLo[rg][0] = *(uint32_t*)&uLo[i0];
                aLo[rg][1] = *(uint32_t*)&uLo[i1];
                aLo[rg][2] = *(uint32_t*)&uLo[i0 + 8];
                aLo[rg][3] = *(uint32_t*)&uLo[i1 + 8];
            }
#pragma unroll
            for (int nt = 0; nt < 8; nt++) {
                int bi = (nt * 8 + g) * S1_STRIDE + kbb + tg * 2;
                uint32_t b0h = *(uint32_t*)&bHi[bi];
                uint32_t b1h = *(uint32_t*)&bHi[bi + 8];
                uint32_t b0l = *(uint32_t*)&bLo[bi];
                uint32_t b1l = *(uint32_t*)&bLo[bi + 8];
#pragma unroll
                for (int rg = 0; rg < 2; rg++) {
                    mma_bf16(acc[rg][nt], aHi[rg][0], aHi[rg][1], aHi[rg][2], aHi[rg][3], b0h, b1h);
                    mma_bf16(acc[rg][nt], aHi[rg][0], aHi[rg][1], aHi[rg][2], aHi[rg][3], b0l, b1l);
                    mma_bf16(acc[rg][nt], aLo[rg][0], aLo[rg][1], aLo[rg][2], aLo[rg][3], b0h, b1h);
                }
            }
        }
    }

    // ======= relu + store to h_out =======
#pragma unroll
    for (int rg = 0; rg < 2; rg++) {
        int r1 = row0 + warpRow + rg * 16 + g;
        int r2 = r1 + 8;
#pragma unroll
        for (int nt = 0; nt < 8; nt++) {
            int col = nt * 8 + tg * 2;
            if (r1 < n)
                *(float2*)&h_out[(size_t)r1 * CC + col] =
                    make_float2(fmaxf(acc[rg][nt][0], 0.f), fmaxf(acc[rg][nt][1], 0.f));
            if (r2 < n)
                *(float2*)&h_out[(size_t)r2 * CC + col] =
                    make_float2(fmaxf(acc[rg][nt][2], 0.f), fmaxf(acc[rg][nt][3], 0.f));
        }
    }
}

// ---------------- SpMM hop: warp per dst row (no gating) ----------------
__global__ __launch_bounds__(256) void spmm_kernel(const float* __restrict__ cur,
                                                   float* __restrict__ nxt, int n) {
    int w = (blockIdx.x * blockDim.x + threadIdx.x) >> 5;
    int lane = threadIdx.x & 31;
    if (w >= n) return;

    int beg = g_rowptr[w];
    int end = g_rowptr[w + 1];
    float a0 = 0.f, a1 = 0.f;

    int e = beg;
    for (; e + 1 < end; e += 2) {
        int2 e0 = g_edges[e];
        int2 e1 = g_edges[e + 1];
        float2 v0 = *(const float2*)&cur[(size_t)e0.x * CC + lane * 2];
        float2 v1 = *(const float2*)&cur[(size_t)e1.x * CC + lane * 2];
        float w0 = __int_as_float(e0.y);
        float w1 = __int_as_float(e1.y);
        a0 = fmaf(w0, v0.x, a0); a1 = fmaf(w0, v0.y, a1);
        a0 = fmaf(w1, v1.x, a0); a1 = fmaf(w1, v1.y, a1);
    }
    if (e < end) {
        int2 e0 = g_edges[e];
        float2 v0 = *(const float2*)&cur[(size_t)e0.x * CC + lane * 2];
        float w0 = __int_as_float(e0.y);
        a0 = fmaf(w0, v0.x, a0); a1 = fmaf(w0, v0.y, a1);
    }

    *(float2*)&nxt[(size_t)w * CC + lane * 2] = make_float2(a0, a1);
}

// ---------------- final: gating + gather for the 10k requested nodes only ----------------
__global__ void gate_gather_kernel(const int* __restrict__ idx,
                                   const float* __restrict__ wp,
                                   float* __restrict__ out, int ni) {
    int w = (blockIdx.x * blockDim.x + threadIdx.x) >> 5;
    int lane = threadIdx.x & 31;
    if (w >= ni) return;
    int nd = idx[w];
    float wpx = __ldg(&wp[lane * 2]);
    float wpy = __ldg(&wp[lane * 2 + 1]);
    float ax = 0.f, ay = 0.f;
#pragma unroll
    for (int k = 0; k <= KHOPS; k++) {
        float2 v = *(const float2*)&g_H[(size_t)k * NN * CC + (size_t)nd * CC + lane * 2];
        float p = v.x * wpx + v.y * wpy;
#pragma unroll
        for (int o = 16; o; o >>= 1) p += __shfl_xor_sync(0xffffffffu, p, o);
        float s = 1.f / (1.f + __expf(-p));
        ax = fmaf(s, v.x, ax);
        ay = fmaf(s, v.y, ay);
    }
    *(float2*)&out[(size_t)w * CC + lane * 2] = make_float2(ax, ay);
}

extern "C" void kernel_launch(void* const* d_in, const int* in_sizes, int n_in,
                              void* d_out, int out_size) {
    const float* x    = (const float*)d_in[0];
    const int*   esrc = (const int*)d_in[1];
    const int*   edst = (const int*)d_in[2];
    const float* ew   = (const float*)d_in[3];
    const int*   nidx = (const int*)d_in[4];
    const float* W1   = (const float*)d_in[5];
    const float* W2   = (const float*)d_in[6];
    const float* wp   = (const float*)d_in[7];

    int N  = in_sizes[0] / DD;
    int E  = in_sizes[1];
    int NI = in_sizes[4];

    float* H0;
    cudaGetSymbolAddress((void**)&H0, g_H);

    cudaFuncSetAttribute(mlp_mma_kernel,
                         cudaFuncAttributeMaxDynamicSharedMemorySize, MLP_SMEM);

    // CSR-by-dst build (re-done every replay; device state must be reset)
    zero_kernel<<<(N + 255) / 256, 256>>>(N);
    count_kernel<<<(E + 255) / 256, 256>>>(edst, E);
    scan_kernel<<<1, 1024>>>(N);
    fill_kernel<<<(E + 255) / 256, 256>>>(esrc, edst, ew, E);

    // MLP -> H[0] (tensor cores, bf16-split)
    mlp_mma_kernel<<<(N + 255) / 256, 256, MLP_SMEM>>>(x, W1, W2, H0, N);

    // 10 propagation hops: H[k] -> H[k+1]
    for (int k = 0; k < KHOPS; k++)
        spmm_kernel<<<(N * 32 + 255) / 256, 256>>>(H0 + (size_t)k * NN * CC,
                                                   H0 + (size_t)(k + 1) * NN * CC, N);

    // gating + gather only for requested nodes
    gate_gather_kernel<<<(NI * 32 + 255) / 256, 256>>>(nidx, wp, (float*)d_out, NI);
}